// round 1
// baseline (speedup 1.0000x reference)
#include <cuda_runtime.h>
#include <cuda_bf16.h>
#include <cstdint>

// ---------------- problem dims (fixed by dataset) ----------------
#define T_STEPS 512
#define BATCH   128
#define SDIM    1024
#define ODIM    256
#define JDIM    (SDIM + ODIM)   // 1280

// ---------------- tiling ----------------
#define NB 4                 // batch tiles
#define NJ 32                // j tiles
#define BT 32                // batch rows per CTA   (128/NB)
#define JT 40                // j cols per CTA       (1280/NJ)
#define NCTAS (NB * NJ)      // 128 CTAs, one per SM, all co-resident
#define NTHREADS 256
#define NWARPS 8
#define KSLICE 128           // K slice per warp (split-K over 8 warps)
#define PAD 8                // bf16 pad per smem row (16B)
#define GSTRIDE (SDIM + PAD) // 1032 halves per smem row
#define GW (GSTRIDE / 2)     // 516 words per smem row

// smem layout (bytes)
#define SW_BYTES (JT * GSTRIDE * 2)            // 82560
#define SG_BYTES (BT * GSTRIDE * 2)            // 66048
#define SP_BYTES (NWARPS * BT * JT * 4)        // 40960
#define SH_BYTES (BT * JT * 4)                 // 5120
#define SB_BYTES (JT * 4)                      // 160
#define SMEM_TOTAL (SW_BYTES + SG_BYTES + SP_BYTES + SH_BYTES + SB_BYTES)

// ---------------- device globals (scratch; no allocation allowed) ----------------
__device__ __align__(16) __nv_bfloat16 g_W[(size_t)JDIM * SDIM];      // concat(w_r, w_o), bf16
__device__ __align__(16) __nv_bfloat16 g_G[2][(size_t)BATCH * SDIM];  // tanh(h), double-buffered
__device__ unsigned g_cnt;
__device__ unsigned g_release;

// ---------------- helpers ----------------
__device__ __forceinline__ unsigned ld_acq(const unsigned* p) {
    unsigned v;
    asm volatile("ld.acquire.gpu.global.u32 %0, [%1];" : "=r"(v) : "l"(p));
    return v;
}
__device__ __forceinline__ void st_rel(unsigned* p, unsigned v) {
    asm volatile("st.release.gpu.global.u32 [%0], %1;" :: "l"(p), "r"(v) : "memory");
}

// one-per-step grid barrier; phase starts at 1 and increments each call.
__device__ __forceinline__ void grid_sync(unsigned phase) {
    __syncthreads();
    if (threadIdx.x == 0) {
        __threadfence();
        unsigned old = atomicAdd(&g_cnt, 1u);
        if (old == phase * (unsigned)NCTAS - 1u) {
            st_rel(&g_release, phase);
        } else {
            while (ld_acq(&g_release) < phase) { }
        }
    }
    __syncthreads();
}

__device__ __forceinline__ void mma16816(float c[4], const unsigned a[4],
                                         unsigned b0, unsigned b1) {
    asm volatile(
        "mma.sync.aligned.m16n8k16.row.col.f32.bf16.bf16.f32 "
        "{%0,%1,%2,%3}, {%4,%5,%6,%7}, {%8,%9}, {%0,%1,%2,%3};\n"
        : "+f"(c[0]), "+f"(c[1]), "+f"(c[2]), "+f"(c[3])
        : "r"(a[0]), "r"(a[1]), "r"(a[2]), "r"(a[3]), "r"(b0), "r"(b1));
}

// ---------------- init: bf16 weights + G0 = tanh(h_init), reset barrier ----------------
__global__ void trnn_init(const float* __restrict__ w_r, const float* __restrict__ w_o,
                          const float* __restrict__ h_init) {
    size_t stride = (size_t)gridDim.x * blockDim.x;
    size_t i0 = (size_t)blockIdx.x * blockDim.x + threadIdx.x;
    const size_t WR_N = (size_t)SDIM * SDIM;
    const size_t W_N  = (size_t)JDIM * SDIM;
    for (size_t i = i0; i < W_N; i += stride) {
        float v = (i < WR_N) ? w_r[i] : w_o[i - WR_N];
        g_W[i] = __float2bfloat16(v);
    }
    for (size_t i = i0; i < (size_t)BATCH * SDIM; i += stride) {
        g_G[0][i] = __float2bfloat16(tanhf(h_init[i]));
    }
    if (i0 == 0) { g_cnt = 0u; g_release = 0u; }
}

// ---------------- persistent kernel ----------------
__global__ void __launch_bounds__(NTHREADS, 1)
trnn_persistent(const float* __restrict__ x, const float* __restrict__ h_init,
                const float* __restrict__ b_r, const float* __restrict__ b_o,
                float* __restrict__ out) {
    extern __shared__ char smem[];
    __nv_bfloat16* sW = (__nv_bfloat16*)smem;
    __nv_bfloat16* sG = (__nv_bfloat16*)(smem + SW_BYTES);
    float* sP = (float*)(smem + SW_BYTES + SG_BYTES);
    float* sH = (float*)(smem + SW_BYTES + SG_BYTES + SP_BYTES);
    float* sB = (float*)(smem + SW_BYTES + SG_BYTES + SP_BYTES + SH_BYTES);

    const int tid  = threadIdx.x;
    const int warp = tid >> 5;
    const int lane = tid & 31;
    const int grp  = lane >> 2;   // 0..7
    const int tig  = lane & 3;    // 0..3
    const int btile = blockIdx.x >> 5;  // /NJ
    const int jtile = blockIdx.x & 31;  // %NJ
    const int b0 = btile * BT;
    const int j0 = jtile * JT;
    const int kw = warp * KSLICE;

    // --- load W tile (resident across all steps): 40 rows x 1024 bf16 ---
    for (int i = tid; i < JT * (SDIM / 8); i += NTHREADS) {   // 5120 uint4
        int r = i >> 7, c = i & 127;
        uint4 v = *(const uint4*)(g_W + (size_t)(j0 + r) * SDIM + c * 8);
        *(uint4*)(sW + r * GSTRIDE + c * 8) = v;
    }
    // --- h tile (fp32, resident) + bias slice ---
    for (int i = tid; i < BT * JT; i += NTHREADS) {
        int bl = i / JT, jl = i - bl * JT;
        int j = j0 + jl;
        sH[i] = (j < SDIM) ? h_init[(size_t)(b0 + bl) * SDIM + j] : 0.f;
    }
    for (int i = tid; i < JT; i += NTHREADS) {
        int j = j0 + i;
        sB[i] = (j < SDIM) ? b_r[j] : b_o[j - SDIM];
    }
    __syncthreads();

    const unsigned* sG32 = (const unsigned*)sG;
    const unsigned* sW32 = (const unsigned*)sW;

    for (int it = 0; it <= T_STEPS; ++it) {
        // --- warp-private load of G[0:32][kw : kw+128) via cp.async.cg (L1-bypassing) ---
        const __nv_bfloat16* Gc = g_G[it & 1];
        #pragma unroll
        for (int ii = 0; ii < 16; ++ii) {
            int q = ii * 32 + lane;      // 0..511 pieces of 16B
            int r = q >> 4;              // row 0..31
            int pc = q & 15;             // piece within 256B row-slice
            const __nv_bfloat16* gp = Gc + (size_t)(b0 + r) * SDIM + kw + pc * 8;
            unsigned sa = (unsigned)__cvta_generic_to_shared(sG + r * GSTRIDE + kw + pc * 8);
            asm volatile("cp.async.cg.shared.global [%0], [%1], 16;\n" :: "r"(sa), "l"(gp));
        }
        asm volatile("cp.async.commit_group;\n" ::);
        asm volatile("cp.async.wait_group 0;\n" ::);
        __syncwarp();

        // --- split-K mma: this warp covers K in [kw, kw+128) for the full 32x40 tile ---
        float acc[2][5][4];
        #pragma unroll
        for (int mi = 0; mi < 2; ++mi)
            #pragma unroll
            for (int ni = 0; ni < 5; ++ni)
                #pragma unroll
                for (int q = 0; q < 4; ++q) acc[mi][ni][q] = 0.f;

        #pragma unroll
        for (int ks = 0; ks < KSLICE / 16; ++ks) {
            const int kwrd = (kw >> 1) + ks * 8;   // word index of k-step base
            unsigned a[2][4];
            #pragma unroll
            for (int mi = 0; mi < 2; ++mi) {
                int r = mi * 16 + grp;
                a[mi][0] = sG32[r * GW + kwrd + tig];
                a[mi][1] = sG32[(r + 8) * GW + kwrd + tig];
                a[mi][2] = sG32[r * GW + kwrd + 4 + tig];
                a[mi][3] = sG32[(r + 8) * GW + kwrd + 4 + tig];
            }
            #pragma unroll
            for (int ni = 0; ni < 5; ++ni) {
                int jr = ni * 8 + grp;
                unsigned bb0 = sW32[jr * GW + kwrd + tig];
                unsigned bb1 = sW32[jr * GW + kwrd + 4 + tig];
                mma16816(acc[0][ni], a[0], bb0, bb1);
                mma16816(acc[1][ni], a[1], bb0, bb1);
            }
        }

        // --- write per-warp partials ---
        {
            float* p = sP + warp * (BT * JT);
            #pragma unroll
            for (int mi = 0; mi < 2; ++mi)
                #pragma unroll
                for (int ni = 0; ni < 5; ++ni) {
                    int r = mi * 16 + grp, cc = ni * 8 + tig * 2;
                    *(float2*)&p[r * JT + cc]       = make_float2(acc[mi][ni][0], acc[mi][ni][1]);
                    *(float2*)&p[(r + 8) * JT + cc] = make_float2(acc[mi][ni][2], acc[mi][ni][3]);
                }
        }
        __syncthreads();

        // --- split-K reduction + fused epilogue (h update / tanh / output) ---
        __nv_bfloat16* Gn = g_G[(it + 1) & 1];
        #pragma unroll
        for (int d = 0; d < 5; ++d) {
            int e = d * NTHREADS + tid;     // 0..1279
            float y = sP[e];
            #pragma unroll
            for (int w = 1; w < NWARPS; ++w) y += sP[w * (BT * JT) + e];
            int bl = e / JT, jl = e - bl * JT;
            int j = j0 + jl, b = b0 + bl;
            if (j < SDIM) {
                float hv = 0.75f * sH[e] + 0.25f * (y + sB[jl]);
                sH[e] = hv;
                Gn[(size_t)b * SDIM + j] = __float2bfloat16(tanhf(hv));
            } else if (it >= 1) {
                int o = j - SDIM;
                size_t oi = ((size_t)(it - 1) * BATCH + b) * ODIM + o;
                out[oi] = y + sB[jl] - x[oi];
            }
        }

        grid_sync((unsigned)(it + 1));
    }
}

// ---------------- launch ----------------
extern "C" void kernel_launch(void* const* d_in, const int* in_sizes, int n_in,
                              void* d_out, int out_size) {
    const float *x = nullptr, *h = nullptr, *wr = nullptr, *br = nullptr,
                *wo = nullptr, *bo = nullptr;
    for (int i = 0; i < n_in; ++i) {
        switch (in_sizes[i]) {
            case 512 * 128 * 256: x  = (const float*)d_in[i]; break;  // 16777216
            case 128 * 1024:      h  = (const float*)d_in[i]; break;  // 131072
            case 1024 * 1024:     wr = (const float*)d_in[i]; break;  // 1048576
            case 1024:            br = (const float*)d_in[i]; break;
            case 256 * 1024:      wo = (const float*)d_in[i]; break;  // 262144
            case 256:             bo = (const float*)d_in[i]; break;
            default: break;
        }
    }
    cudaFuncSetAttribute(trnn_persistent,
                         cudaFuncAttributeMaxDynamicSharedMemorySize, SMEM_TOTAL);
    trnn_init<<<512, 256>>>(wr, wo, h);
    trnn_persistent<<<NCTAS, NTHREADS, SMEM_TOTAL>>>(x, h, br, bo, (float*)d_out);
}

// round 2
// speedup vs baseline: 1.5296x; 1.5296x over previous
#include <cuda_runtime.h>
#include <cuda_bf16.h>
#include <cstdint>

// ---------------- problem dims (fixed by dataset) ----------------
#define T_STEPS 512
#define BATCH   128
#define SDIM    1024
#define ODIM    256
#define JDIM    (SDIM + ODIM)   // 1280

// ---------------- tiling ----------------
#define NB 4                 // batch tiles (independent recurrence groups)
#define NJ 32                // j tiles
#define BT 32                // batch rows per CTA   (128/NB)
#define JT 40                // j cols per CTA       (1280/NJ)
#define NCTAS (NB * NJ)      // 128 CTAs, one per SM, all co-resident
#define NTHREADS 256
#define NWARPS 8
#define KSLICE 128           // K slice per warp (split-K over 8 warps)
#define PAD 8                // bf16 pad per smem row (16B)
#define GSTRIDE (SDIM + PAD) // 1032 halves per smem row
#define GW (GSTRIDE / 2)     // 516 words per smem row

// smem layout (bytes): G tile + split-K partials only
#define SG_BYTES (BT * GSTRIDE * 2)            // 66048
#define SP_BYTES (NWARPS * BT * JT * 4)        // 40960
#define SMEM_TOTAL (SG_BYTES + SP_BYTES)       // 107008

// ---------------- device globals (scratch; no allocation allowed) ----------------
__device__ __align__(16) __nv_bfloat16 g_W[(size_t)JDIM * SDIM];      // concat(w_r, w_o), bf16
__device__ __align__(16) __nv_bfloat16 g_G[2][(size_t)BATCH * SDIM];  // tanh(h), double-buffered
__device__ unsigned g_cnt4[4 * 32];   // per-btile-group arrival counters (cacheline-padded)
__device__ unsigned g_rel4[4 * 32];   // per-btile-group release phases

// ---------------- helpers ----------------
__device__ __forceinline__ unsigned ld_acq(const unsigned* p) {
    unsigned v;
    asm volatile("ld.acquire.gpu.global.u32 %0, [%1];" : "=r"(v) : "l"(p));
    return v;
}
__device__ __forceinline__ void st_rel(unsigned* p, unsigned v) {
    asm volatile("st.release.gpu.global.u32 [%0], %1;" :: "l"(p), "r"(v) : "memory");
}

__device__ __forceinline__ void mma16816(float c[4], const unsigned a[4],
                                         unsigned b0, unsigned b1) {
    asm volatile(
        "mma.sync.aligned.m16n8k16.row.col.f32.bf16.bf16.f32 "
        "{%0,%1,%2,%3}, {%4,%5,%6,%7}, {%8,%9}, {%0,%1,%2,%3};\n"
        : "+f"(c[0]), "+f"(c[1]), "+f"(c[2]), "+f"(c[3])
        : "r"(a[0]), "r"(a[1]), "r"(a[2]), "r"(a[3]), "r"(b0), "r"(b1));
}

// ---------------- init: bf16 weights + G0 = tanh(h_init), reset barriers ----------------
__global__ void trnn_init(const float* __restrict__ w_r, const float* __restrict__ w_o,
                          const float* __restrict__ h_init) {
    size_t stride = (size_t)gridDim.x * blockDim.x;
    size_t i0 = (size_t)blockIdx.x * blockDim.x + threadIdx.x;
    const size_t WR_N = (size_t)SDIM * SDIM;
    const size_t W_N  = (size_t)JDIM * SDIM;
    for (size_t i = i0; i < W_N; i += stride) {
        float v = (i < WR_N) ? w_r[i] : w_o[i - WR_N];
        g_W[i] = __float2bfloat16(v);
    }
    for (size_t i = i0; i < (size_t)BATCH * SDIM; i += stride) {
        g_G[0][i] = __float2bfloat16(tanhf(h_init[i]));
    }
    if (i0 < 4 * 32) { g_cnt4[i0] = 0u; g_rel4[i0] = 0u; }
}

// ---------------- persistent kernel ----------------
__global__ void __launch_bounds__(NTHREADS, 1)
trnn_persistent(const float* __restrict__ x, const float* __restrict__ h_init,
                const float* __restrict__ b_r, const float* __restrict__ b_o,
                float* __restrict__ out) {
    extern __shared__ char smem[];
    __nv_bfloat16* sG = (__nv_bfloat16*)smem;
    float* sP = (float*)(smem + SG_BYTES);

    const int tid  = threadIdx.x;
    const int warp = tid >> 5;
    const int lane = tid & 31;
    const int grp  = lane >> 2;   // 0..7
    const int tig  = lane & 3;    // 0..3
    const int btile = blockIdx.x >> 5;  // /NJ
    const int jtile = blockIdx.x & 31;  // %NJ
    const int b0 = btile * BT;
    const int j0 = jtile * JT;
    const int kw = warp * KSLICE;

    unsigned* my_cnt = &g_cnt4[btile * 32];
    unsigned* my_rel = &g_rel4[btile * 32];

    // --- per-thread persistent epilogue indices + state (same element every step) ---
    int ej[5]; int ebl[5]; float hr[5]; float bv[5];
    #pragma unroll
    for (int d = 0; d < 5; ++d) {
        int e = d * NTHREADS + tid;
        int bl = e / JT;
        int jl = e - bl * JT;
        int j = j0 + jl;
        ej[d] = j; ebl[d] = bl;
        if (j < SDIM) {
            hr[d] = h_init[(size_t)(b0 + bl) * SDIM + j];
            bv[d] = b_r[j];
        } else {
            hr[d] = 0.f;
            bv[d] = b_o[j - SDIM];
        }
    }

    // --- W fragments: persistent in registers across all steps (80 regs/thread) ---
    unsigned Breg[8][5][2];
    #pragma unroll
    for (int ks = 0; ks < 8; ++ks) {
        #pragma unroll
        for (int ni = 0; ni < 5; ++ni) {
            int jr = ni * 8 + grp;
            const unsigned* wp = (const unsigned*)(g_W + (size_t)(j0 + jr) * SDIM + kw + ks * 16);
            Breg[ks][ni][0] = wp[tig];
            Breg[ks][ni][1] = wp[4 + tig];
        }
    }
    __syncthreads();

    const unsigned* sG32 = (const unsigned*)sG;

    for (int it = 0; it <= T_STEPS; ++it) {
        // --- warp-private G load (L1-bypassing), split into 2 K-chunks for pipelining ---
        const __nv_bfloat16* Gc = g_G[it & 1];
        #pragma unroll
        for (int c = 0; c < 2; ++c) {
            #pragma unroll
            for (int ii = 0; ii < 8; ++ii) {
                int p = ii * 32 + lane;      // 0..255
                int r = p >> 3;              // row 0..31
                int pc = c * 8 + (p & 7);    // 16B piece 0..15
                const __nv_bfloat16* gp = Gc + (size_t)(b0 + r) * SDIM + kw + pc * 8;
                unsigned sa = (unsigned)__cvta_generic_to_shared(sG + r * GSTRIDE + kw + pc * 8);
                asm volatile("cp.async.cg.shared.global [%0], [%1], 16;\n" :: "r"(sa), "l"(gp));
            }
            asm volatile("cp.async.commit_group;\n" ::);
        }

        // --- prefetch x for this step's outputs (hidden behind mma) ---
        float xr[5];
        if (it >= 1) {
            #pragma unroll
            for (int d = 0; d < 5; ++d) {
                if (ej[d] >= SDIM) {
                    size_t oi = ((size_t)(it - 1) * BATCH + (b0 + ebl[d])) * ODIM + (ej[d] - SDIM);
                    xr[d] = __ldcs(x + oi);
                }
            }
        }

        float acc[2][5][4];
        #pragma unroll
        for (int mi = 0; mi < 2; ++mi)
            #pragma unroll
            for (int ni = 0; ni < 5; ++ni)
                #pragma unroll
                for (int q = 0; q < 4; ++q) acc[mi][ni][q] = 0.f;

        // chunk 0 ready
        asm volatile("cp.async.wait_group 1;\n" ::);
        __syncwarp();
        #pragma unroll
        for (int ks = 0; ks < 4; ++ks) {
            const int kwrd = (kw >> 1) + ks * 8;
            unsigned a[2][4];
            #pragma unroll
            for (int mi = 0; mi < 2; ++mi) {
                int r = mi * 16 + grp;
                a[mi][0] = sG32[r * GW + kwrd + tig];
                a[mi][1] = sG32[(r + 8) * GW + kwrd + tig];
                a[mi][2] = sG32[r * GW + kwrd + 4 + tig];
                a[mi][3] = sG32[(r + 8) * GW + kwrd + 4 + tig];
            }
            #pragma unroll
            for (int ni = 0; ni < 5; ++ni) {
                mma16816(acc[0][ni], a[0], Breg[ks][ni][0], Breg[ks][ni][1]);
                mma16816(acc[1][ni], a[1], Breg[ks][ni][0], Breg[ks][ni][1]);
            }
        }
        // chunk 1 ready
        asm volatile("cp.async.wait_group 0;\n" ::);
        __syncwarp();
        #pragma unroll
        for (int ks = 4; ks < 8; ++ks) {
            const int kwrd = (kw >> 1) + ks * 8;
            unsigned a[2][4];
            #pragma unroll
            for (int mi = 0; mi < 2; ++mi) {
                int r = mi * 16 + grp;
                a[mi][0] = sG32[r * GW + kwrd + tig];
                a[mi][1] = sG32[(r + 8) * GW + kwrd + tig];
                a[mi][2] = sG32[r * GW + kwrd + 4 + tig];
                a[mi][3] = sG32[(r + 8) * GW + kwrd + 4 + tig];
            }
            #pragma unroll
            for (int ni = 0; ni < 5; ++ni) {
                mma16816(acc[0][ni], a[0], Breg[ks][ni][0], Breg[ks][ni][1]);
                mma16816(acc[1][ni], a[1], Breg[ks][ni][0], Breg[ks][ni][1]);
            }
        }

        // --- write per-warp partials ---
        {
            float* p = sP + warp * (BT * JT);
            #pragma unroll
            for (int mi = 0; mi < 2; ++mi)
                #pragma unroll
                for (int ni = 0; ni < 5; ++ni) {
                    int r = mi * 16 + grp, cc = ni * 8 + tig * 2;
                    *(float2*)&p[r * JT + cc]       = make_float2(acc[mi][ni][0], acc[mi][ni][1]);
                    *(float2*)&p[(r + 8) * JT + cc] = make_float2(acc[mi][ni][2], acc[mi][ni][3]);
                }
        }
        __syncthreads();

        // --- pass 1: split-K reduce; h update + tanh + G store (critical path) ---
        __nv_bfloat16* Gn = g_G[(it + 1) & 1];
        float yv[5];
        #pragma unroll
        for (int d = 0; d < 5; ++d) {
            int e = d * NTHREADS + tid;
            float y = sP[e];
            #pragma unroll
            for (int w = 1; w < NWARPS; ++w) y += sP[w * (BT * JT) + e];
            yv[d] = y;
            if (ej[d] < SDIM) {
                float hv = 0.75f * hr[d] + 0.25f * (y + bv[d]);
                hr[d] = hv;
                Gn[(size_t)(b0 + ebl[d]) * SDIM + ej[d]] = __float2bfloat16(tanhf(hv));
            }
        }
        __syncthreads();

        // --- arrive at the group barrier ASAP (outputs are off the critical path) ---
        const unsigned phase = (unsigned)(it + 1);
        if (tid == 0) {
            __threadfence();
            unsigned old = atomicAdd(my_cnt, 1u);
            if (old == phase * 32u - 1u) st_rel(my_rel, phase);
        }

        // --- pass 2: outputs (x already prefetched) ---
        if (it >= 1) {
            #pragma unroll
            for (int d = 0; d < 5; ++d) {
                if (ej[d] >= SDIM) {
                    size_t oi = ((size_t)(it - 1) * BATCH + (b0 + ebl[d])) * ODIM + (ej[d] - SDIM);
                    out[oi] = yv[d] + bv[d] - xr[d];
                }
            }
        }

        // --- wait for group release ---
        if (tid == 0) {
            while (ld_acq(my_rel) < phase) { }
        }
        __syncthreads();
    }
}

// ---------------- launch ----------------
extern "C" void kernel_launch(void* const* d_in, const int* in_sizes, int n_in,
                              void* d_out, int out_size) {
    const float *x = nullptr, *h = nullptr, *wr = nullptr, *br = nullptr,
                *wo = nullptr, *bo = nullptr;
    for (int i = 0; i < n_in; ++i) {
        switch (in_sizes[i]) {
            case 512 * 128 * 256: x  = (const float*)d_in[i]; break;  // 16777216
            case 128 * 1024:      h  = (const float*)d_in[i]; break;  // 131072
            case 1024 * 1024:     wr = (const float*)d_in[i]; break;  // 1048576
            case 1024:            br = (const float*)d_in[i]; break;
            case 256 * 1024:      wo = (const float*)d_in[i]; break;  // 262144
            case 256:             bo = (const float*)d_in[i]; break;
            default: break;
        }
    }
    cudaFuncSetAttribute(trnn_persistent,
                         cudaFuncAttributeMaxDynamicSharedMemorySize, SMEM_TOTAL);
    trnn_init<<<512, 256>>>(wr, wo, h);
    trnn_persistent<<<NCTAS, NTHREADS, SMEM_TOTAL>>>(x, h, br, bo, (float*)d_out);
}

// round 3
// speedup vs baseline: 1.9377x; 1.2668x over previous
#include <cuda_runtime.h>
#include <cuda_bf16.h>
#include <cstdint>

// ---------------- problem dims (fixed by dataset) ----------------
#define T_STEPS 512
#define BATCH   128
#define SDIM    1024
#define ODIM    256
#define JDIM    (SDIM + ODIM)   // 1280

// ---------------- tiling ----------------
#define NB 4                 // batch tiles (independent recurrence groups)
#define NJ 32                // j tiles
#define BT 32                // batch rows per CTA   (128/NB)
#define JT 40                // j cols per CTA       (1280/NJ)
#define NCTAS (NB * NJ)      // 128 CTAs, one per SM, all co-resident
#define NTHREADS 256
#define NWARPS 8
#define KSLICE 128           // K slice per warp (split-K over 8 warps)
#define CLUSTER 4            // multicast group (same btile; 32 % 4 == 0)
#define ROWS_PER_CTA (BT / CLUSTER)   // 8 G-rows loaded+multicast per CTA
#define PAD 8                // bf16 pad per smem row (16B)
#define GSTRIDE (SDIM + PAD) // 1032 halves per smem row
#define GW (GSTRIDE / 2)     // 516 words per smem row
#define ROW_BYTES (SDIM * 2) // 2048 contiguous bytes per G row in gmem

// smem layout (bytes)
#define SG_BYTES (BT * GSTRIDE * 2)            // 66048
#define SP_BYTES (NWARPS * BT * JT * 4)        // 40960
#define SMEM_TOTAL (SG_BYTES + SP_BYTES + 16)  // + mbarrier

// ---------------- device globals (scratch; no allocation allowed) ----------------
__device__ __align__(16) __nv_bfloat16 g_W[(size_t)JDIM * SDIM];      // concat(w_r, w_o), bf16
__device__ __align__(16) __nv_bfloat16 g_G[2][(size_t)BATCH * SDIM];  // tanh(h), double-buffered
__device__ unsigned g_slots[NB * 32];  // per-CTA arrival slots (phase values)

// ---------------- helpers ----------------
__device__ __forceinline__ unsigned ld_acq(const unsigned* p) {
    unsigned v;
    asm volatile("ld.acquire.gpu.global.u32 %0, [%1];" : "=r"(v) : "l"(p));
    return v;
}
__device__ __forceinline__ void st_rel(unsigned* p, unsigned v) {
    asm volatile("st.release.gpu.global.u32 [%0], %1;" :: "l"(p), "r"(v) : "memory");
}
__device__ __forceinline__ void mma16816(float c[4], const unsigned a[4],
                                         unsigned b0, unsigned b1) {
    asm volatile(
        "mma.sync.aligned.m16n8k16.row.col.f32.bf16.bf16.f32 "
        "{%0,%1,%2,%3}, {%4,%5,%6,%7}, {%8,%9}, {%0,%1,%2,%3};\n"
        : "+f"(c[0]), "+f"(c[1]), "+f"(c[2]), "+f"(c[3])
        : "r"(a[0]), "r"(a[1]), "r"(a[2]), "r"(a[3]), "r"(b0), "r"(b1));
}

// ---------------- init: bf16 weights + G0 = tanh(h_init), reset barrier slots ----------------
__global__ void trnn_init(const float* __restrict__ w_r, const float* __restrict__ w_o,
                          const float* __restrict__ h_init) {
    size_t stride = (size_t)gridDim.x * blockDim.x;
    size_t i0 = (size_t)blockIdx.x * blockDim.x + threadIdx.x;
    const size_t WR_N = (size_t)SDIM * SDIM;
    const size_t W_N  = (size_t)JDIM * SDIM;
    for (size_t i = i0; i < W_N; i += stride) {
        float v = (i < WR_N) ? w_r[i] : w_o[i - WR_N];
        g_W[i] = __float2bfloat16(v);
    }
    for (size_t i = i0; i < (size_t)BATCH * SDIM; i += stride) {
        g_G[0][i] = __float2bfloat16(tanhf(h_init[i]));
    }
    if (i0 < NB * 32) g_slots[i0] = 0u;
}

// ---------------- persistent kernel (cluster = 4, multicast G) ----------------
__global__ void __launch_bounds__(NTHREADS, 1) __cluster_dims__(CLUSTER, 1, 1)
trnn_persistent(const float* __restrict__ x, const float* __restrict__ h_init,
                const float* __restrict__ b_r, const float* __restrict__ b_o,
                float* __restrict__ out) {
    extern __shared__ char smem[];
    __nv_bfloat16* sG = (__nv_bfloat16*)smem;
    float* sP = (float*)(smem + SG_BYTES);
    uint32_t mbar = (uint32_t)__cvta_generic_to_shared(smem + SG_BYTES + SP_BYTES);

    const int tid  = threadIdx.x;
    const int warp = tid >> 5;
    const int lane = tid & 31;
    const int grp  = lane >> 2;   // 0..7
    const int tig  = lane & 3;    // 0..3
    const int btile = blockIdx.x >> 5;  // /NJ
    const int jtile = blockIdx.x & 31;  // %NJ
    const int rank  = blockIdx.x & (CLUSTER - 1);
    const int b0 = btile * BT;
    const int j0 = jtile * JT;
    const int kw = warp * KSLICE;

    unsigned* grp_slots = &g_slots[btile * 32];

    // mbarrier init (count = 1: the single expect_tx arrival per phase)
    if (tid == 0) {
        asm volatile("mbarrier.init.shared.b64 [%0], 1;" :: "r"(mbar) : "memory");
    }
    __syncthreads();
    // all cluster peers' mbarriers live before any multicast targets them
    asm volatile("barrier.cluster.arrive.aligned;" ::: "memory");
    asm volatile("barrier.cluster.wait.aligned;"   ::: "memory");

    // --- per-thread persistent epilogue indices + state (same element every step) ---
    int ej[5]; int ebl[5]; float hr[5]; float bv[5];
    #pragma unroll
    for (int d = 0; d < 5; ++d) {
        int e = d * NTHREADS + tid;
        int bl = e / JT;
        int jl = e - bl * JT;
        int j = j0 + jl;
        ej[d] = j; ebl[d] = bl;
        if (j < SDIM) {
            hr[d] = h_init[(size_t)(b0 + bl) * SDIM + j];
            bv[d] = b_r[j];
        } else {
            hr[d] = 0.f;
            bv[d] = b_o[j - SDIM];
        }
    }

    // --- W fragments: persistent in registers across all steps (80 regs/thread) ---
    unsigned Breg[8][5][2];
    #pragma unroll
    for (int ks = 0; ks < 8; ++ks) {
        #pragma unroll
        for (int ni = 0; ni < 5; ++ni) {
            int jr = ni * 8 + grp;
            const unsigned* wp = (const unsigned*)(g_W + (size_t)(j0 + jr) * SDIM + kw + ks * 16);
            Breg[ks][ni][0] = wp[tig];
            Breg[ks][ni][1] = wp[4 + tig];
        }
    }
    __syncthreads();

    const unsigned* sG32 = (const unsigned*)sG;

    for (int it = 0; it <= T_STEPS; ++it) {
        // --- wait for group barrier: all 32 CTAs of this btile at phase >= it ---
        if (it > 0) {
            const unsigned phase = (unsigned)it;
            if (warp == 0) {
                for (;;) {
                    unsigned v = ld_acq(&grp_slots[lane]);   // 32 coalesced slots
                    if (__all_sync(0xffffffffu, v >= phase)) break;
                }
            }
            __syncthreads();
        }

        // --- issue multicast bulk loads: this CTA loads 8 rows, delivers to all 4 peers ---
        const __nv_bfloat16* Gc = g_G[it & 1];
        if (tid == 0) {
            asm volatile("fence.proxy.async;" ::: "memory");
            asm volatile("mbarrier.arrive.expect_tx.shared.b64 _, [%0], %1;"
                         :: "r"(mbar), "r"(BT * ROW_BYTES) : "memory");
            #pragma unroll
            for (int rr = 0; rr < ROWS_PER_CTA; ++rr) {
                int r = rank * ROWS_PER_CTA + rr;
                const void* src = (const void*)(Gc + (size_t)(b0 + r) * SDIM);
                uint32_t dst = (uint32_t)__cvta_generic_to_shared(sG + r * GSTRIDE);
                asm volatile(
                    "cp.async.bulk.shared::cluster.global.mbarrier::complete_tx::bytes"
                    ".multicast::cluster [%0], [%1], %2, [%3], %4;"
                    :: "r"(dst), "l"(src), "r"(ROW_BYTES), "r"(mbar),
                       "h"((unsigned short)((1u << CLUSTER) - 1u))
                    : "memory");
            }
        }

        // --- prefetch x for this step's outputs (hidden behind G delivery + mma) ---
        float xr[5];
        if (it >= 1) {
            #pragma unroll
            for (int d = 0; d < 5; ++d) {
                if (ej[d] >= SDIM) {
                    size_t oi = ((size_t)(it - 1) * BATCH + (b0 + ebl[d])) * ODIM + (ej[d] - SDIM);
                    xr[d] = __ldcs(x + oi);
                }
            }
        }

        // --- wait for full 64KB G tile (tx from all 4 cluster CTAs) ---
        {
            const unsigned parity = (unsigned)(it & 1);
            asm volatile(
                "{\n\t"
                ".reg .pred P;\n\t"
                "WL_%=:\n\t"
                "mbarrier.try_wait.parity.acquire.cta.shared::cta.b64 P, [%0], %1, 0x989680;\n\t"
                "@P bra.uni WD_%=;\n\t"
                "bra.uni WL_%=;\n\t"
                "WD_%=:\n\t"
                "}" :: "r"(mbar), "r"(parity) : "memory");
        }

        // --- split-K mma: this warp covers K in [kw, kw+128) for the full 32x40 tile ---
        float acc[2][5][4];
        #pragma unroll
        for (int mi = 0; mi < 2; ++mi)
            #pragma unroll
            for (int ni = 0; ni < 5; ++ni)
                #pragma unroll
                for (int q = 0; q < 4; ++q) acc[mi][ni][q] = 0.f;

        #pragma unroll
        for (int ks = 0; ks < 8; ++ks) {
            const int kwrd = (kw >> 1) + ks * 8;
            unsigned a[2][4];
            #pragma unroll
            for (int mi = 0; mi < 2; ++mi) {
                int r = mi * 16 + grp;
                a[mi][0] = sG32[r * GW + kwrd + tig];
                a[mi][1] = sG32[(r + 8) * GW + kwrd + tig];
                a[mi][2] = sG32[r * GW + kwrd + 4 + tig];
                a[mi][3] = sG32[(r + 8) * GW + kwrd + 4 + tig];
            }
            #pragma unroll
            for (int ni = 0; ni < 5; ++ni) {
                mma16816(acc[0][ni], a[0], Breg[ks][ni][0], Breg[ks][ni][1]);
                mma16816(acc[1][ni], a[1], Breg[ks][ni][0], Breg[ks][ni][1]);
            }
        }

        // --- write per-warp partials ---
        {
            float* p = sP + warp * (BT * JT);
            #pragma unroll
            for (int mi = 0; mi < 2; ++mi)
                #pragma unroll
                for (int ni = 0; ni < 5; ++ni) {
                    int r = mi * 16 + grp, cc = ni * 8 + tig * 2;
                    *(float2*)&p[r * JT + cc]       = make_float2(acc[mi][ni][0], acc[mi][ni][1]);
                    *(float2*)&p[(r + 8) * JT + cc] = make_float2(acc[mi][ni][2], acc[mi][ni][3]);
                }
        }
        __syncthreads();

        // --- split-K reduce; h update + tanh + G store (critical path) ---
        __nv_bfloat16* Gn = g_G[(it + 1) & 1];
        float yv[5];
        #pragma unroll
        for (int d = 0; d < 5; ++d) {
            int e = d * NTHREADS + tid;
            float y = sP[e];
            #pragma unroll
            for (int w = 1; w < NWARPS; ++w) y += sP[w * (BT * JT) + e];
            yv[d] = y;
            if (ej[d] < SDIM) {
                float hv = 0.75f * hr[d] + 0.25f * (y + bv[d]);
                hr[d] = hv;
                Gn[(size_t)(b0 + ebl[d]) * SDIM + ej[d]] = __float2bfloat16(tanhf(hv));
            }
        }
        __syncthreads();

        // --- arrive: own slot, release semantics (G stores made visible) ---
        if (tid == 0) st_rel(&grp_slots[jtile], (unsigned)(it + 1));

        // --- outputs (off the critical path; x already in registers) ---
        if (it >= 1) {
            #pragma unroll
            for (int d = 0; d < 5; ++d) {
                if (ej[d] >= SDIM) {
                    size_t oi = ((size_t)(it - 1) * BATCH + (b0 + ebl[d])) * ODIM + (ej[d] - SDIM);
                    out[oi] = yv[d] + bv[d] - xr[d];
                }
            }
        }
    }

    // no CTA may exit while peers' multicast writes into its smem are possible
    asm volatile("barrier.cluster.arrive.aligned;" ::: "memory");
    asm volatile("barrier.cluster.wait.aligned;"   ::: "memory");
}

// ---------------- launch ----------------
extern "C" void kernel_launch(void* const* d_in, const int* in_sizes, int n_in,
                              void* d_out, int out_size) {
    const float *x = nullptr, *h = nullptr, *wr = nullptr, *br = nullptr,
                *wo = nullptr, *bo = nullptr;
    for (int i = 0; i < n_in; ++i) {
        switch (in_sizes[i]) {
            case 512 * 128 * 256: x  = (const float*)d_in[i]; break;  // 16777216
            case 128 * 1024:      h  = (const float*)d_in[i]; break;  // 131072
            case 1024 * 1024:     wr = (const float*)d_in[i]; break;  // 1048576
            case 1024:            br = (const float*)d_in[i]; break;
            case 256 * 1024:      wo = (const float*)d_in[i]; break;  // 262144
            case 256:             bo = (const float*)d_in[i]; break;
            default: break;
        }
    }
    cudaFuncSetAttribute(trnn_persistent,
                         cudaFuncAttributeMaxDynamicSharedMemorySize, SMEM_TOTAL);
    trnn_init<<<512, 256>>>(wr, wo, h);
    trnn_persistent<<<NCTAS, NTHREADS, SMEM_TOTAL>>>(x, h, br, bo, (float*)d_out);
}

// round 4
// speedup vs baseline: 2.0395x; 1.0525x over previous
#include <cuda_runtime.h>
#include <cuda_bf16.h>
#include <cstdint>

// ---------------- problem dims (fixed by dataset) ----------------
#define T_STEPS 512
#define BATCH   128
#define SDIM    1024
#define ODIM    256
#define JDIM    (SDIM + ODIM)   // 1280

// ---------------- tiling ----------------
#define NB 4                 // batch tiles (independent recurrence groups)
#define NJ 32                // j tiles
#define BT 32                // batch rows per CTA   (128/NB)
#define JT 40                // j cols per CTA       (1280/NJ)
#define NCTAS (NB * NJ)      // 128 CTAs, one per SM, all co-resident
#define NTHREADS 256
#define NWARPS 8
#define KSLICE 128           // K slice per warp (split-K over 8 warps)
#define CLUSTER 4            // multicast group (same btile; 32 % 4 == 0)
#define ROWS_PER_CTA (BT / CLUSTER)   // 8 G-rows loaded+multicast per CTA
#define PAD 8                // bf16 pad per smem row (16B)
#define GSTRIDE (SDIM + PAD) // 1032 halves per smem row
#define GW (GSTRIDE / 2)     // 516 words per smem row
#define ROW_BYTES (SDIM * 2) // 2048 contiguous bytes per G row in gmem
#define NPROD 26             // jtiles 0..25 produce h columns (j0 < 1024)

// smem layout (bytes)
#define SG_BYTES (BT * GSTRIDE * 2)            // 66048
#define SP_BYTES (NWARPS * BT * JT * 4)        // 40960
#define SMEM_TOTAL (SG_BYTES + SP_BYTES + 16)  // + two mbarriers

// ---------------- device globals (scratch; no allocation allowed) ----------------
__device__ __align__(16) __nv_bfloat16 g_W[(size_t)JDIM * SDIM];      // concat(w_r, w_o), bf16
__device__ __align__(16) __nv_bfloat16 g_G[2][(size_t)BATCH * SDIM];  // tanh(h), double-buffered
__device__ unsigned g_slots[NB * 32];  // per-CTA arrival slots (phase values)

// ---------------- helpers ----------------
__device__ __forceinline__ unsigned ld_acq(const unsigned* p) {
    unsigned v;
    asm volatile("ld.acquire.gpu.global.u32 %0, [%1];" : "=r"(v) : "l"(p));
    return v;
}
__device__ __forceinline__ void st_rel(unsigned* p, unsigned v) {
    asm volatile("st.release.gpu.global.u32 [%0], %1;" :: "l"(p), "r"(v) : "memory");
}
__device__ __forceinline__ float tanh_fast(float v) {
    float r;
    asm("tanh.approx.f32 %0, %1;" : "=f"(r) : "f"(v));
    return r;
}
__device__ __forceinline__ void mma16816(float c[4], const unsigned a[4],
                                         unsigned b0, unsigned b1) {
    asm volatile(
        "mma.sync.aligned.m16n8k16.row.col.f32.bf16.bf16.f32 "
        "{%0,%1,%2,%3}, {%4,%5,%6,%7}, {%8,%9}, {%0,%1,%2,%3};\n"
        : "+f"(c[0]), "+f"(c[1]), "+f"(c[2]), "+f"(c[3])
        : "r"(a[0]), "r"(a[1]), "r"(a[2]), "r"(a[3]), "r"(b0), "r"(b1));
}
__device__ __forceinline__ void ldsm_x4(unsigned a[4], uint32_t addr) {
    asm volatile("ldmatrix.sync.aligned.m8n8.x4.shared.b16 {%0,%1,%2,%3}, [%4];"
                 : "=r"(a[0]), "=r"(a[1]), "=r"(a[2]), "=r"(a[3]) : "r"(addr));
}
__device__ __forceinline__ void mbar_wait(uint32_t mbar, unsigned parity) {
    asm volatile(
        "{\n\t"
        ".reg .pred P;\n\t"
        "WL_%=:\n\t"
        "mbarrier.try_wait.parity.acquire.cta.shared::cta.b64 P, [%0], %1, 0x989680;\n\t"
        "@P bra.uni WD_%=;\n\t"
        "bra.uni WL_%=;\n\t"
        "WD_%=:\n\t"
        "}" :: "r"(mbar), "r"(parity) : "memory");
}

// ---------------- init: bf16 weights + G0 = tanh(h_init), reset barrier slots ----------------
__global__ void trnn_init(const float* __restrict__ w_r, const float* __restrict__ w_o,
                          const float* __restrict__ h_init) {
    size_t stride = (size_t)gridDim.x * blockDim.x;
    size_t i0 = (size_t)blockIdx.x * blockDim.x + threadIdx.x;
    const size_t WR_N = (size_t)SDIM * SDIM;
    const size_t W_N  = (size_t)JDIM * SDIM;
    for (size_t i = i0; i < W_N; i += stride) {
        float v = (i < WR_N) ? w_r[i] : w_o[i - WR_N];
        g_W[i] = __float2bfloat16(v);
    }
    for (size_t i = i0; i < (size_t)BATCH * SDIM; i += stride) {
        g_G[0][i] = __float2bfloat16(tanhf(h_init[i]));
    }
    if (i0 < NB * 32) g_slots[i0] = 0u;
}

// ---------------- persistent kernel (cluster = 4, multicast G, split half-barriers) ----------------
__global__ void __launch_bounds__(NTHREADS, 1) __cluster_dims__(CLUSTER, 1, 1)
trnn_persistent(const float* __restrict__ x, const float* __restrict__ h_init,
                const float* __restrict__ b_r, const float* __restrict__ b_o,
                float* __restrict__ out) {
    extern __shared__ char smem[];
    __nv_bfloat16* sG = (__nv_bfloat16*)smem;
    float* sP = (float*)(smem + SG_BYTES);
    uint32_t mbar0 = (uint32_t)__cvta_generic_to_shared(smem + SG_BYTES + SP_BYTES);
    uint32_t mbar1 = mbar0 + 8;

    const int tid  = threadIdx.x;
    const int warp = tid >> 5;
    const int lane = tid & 31;
    const int grp  = lane >> 2;   // 0..7
    const int tig  = lane & 3;    // 0..3
    const int btile = blockIdx.x >> 5;  // /NJ
    const int jtile = blockIdx.x & 31;  // %NJ
    const int rank  = blockIdx.x & (CLUSTER - 1);
    const int b0 = btile * BT;
    const int j0 = jtile * JT;
    const int kw = warp * KSLICE;
    const bool producer = (jtile < NPROD);

    unsigned* grp_slots = &g_slots[btile * 32];

    // two mbarriers: rows 0-15 (ranks 0,1) and rows 16-31 (ranks 2,3); count=1 each
    if (tid == 0) {
        asm volatile("mbarrier.init.shared.b64 [%0], 1;" :: "r"(mbar0) : "memory");
        asm volatile("mbarrier.init.shared.b64 [%0], 1;" :: "r"(mbar1) : "memory");
    }
    __syncthreads();
    asm volatile("barrier.cluster.arrive.aligned;" ::: "memory");
    asm volatile("barrier.cluster.wait.aligned;"   ::: "memory");

    // --- per-thread persistent epilogue indices + state (same element every step) ---
    int ej[5]; int ebl[5]; float hr[5]; float bv[5];
    #pragma unroll
    for (int d = 0; d < 5; ++d) {
        int e = d * NTHREADS + tid;
        int bl = e / JT;
        int jl = e - bl * JT;
        int j = j0 + jl;
        ej[d] = j; ebl[d] = bl;
        if (j < SDIM) {
            hr[d] = h_init[(size_t)(b0 + bl) * SDIM + j];
            bv[d] = b_r[j];
        } else {
            hr[d] = 0.f;
            bv[d] = b_o[j - SDIM];
        }
    }

    // --- W fragments: persistent in registers across all steps (80 regs/thread) ---
    unsigned Breg[8][5][2];
    #pragma unroll
    for (int ks = 0; ks < 8; ++ks) {
        #pragma unroll
        for (int ni = 0; ni < 5; ++ni) {
            int jr = ni * 8 + grp;
            const unsigned* wp = (const unsigned*)(g_W + (size_t)(j0 + jr) * SDIM + kw + ks * 16);
            Breg[ks][ni][0] = wp[tig];
            Breg[ks][ni][1] = wp[4 + tig];
        }
    }
    __syncthreads();

    // --- ldmatrix per-lane base addresses (rows 0-15 / 16-31, lo/hi k-half) ---
    const uint32_t sGb = (uint32_t)__cvta_generic_to_shared(sG);
    const int rl = lane & 15;
    const int khalf = (lane & 16) ? 8 : 0;
    const uint32_t aBase0 = sGb + (uint32_t)((rl * GSTRIDE + kw + khalf) * 2);
    const uint32_t aBase1 = aBase0 + (uint32_t)(16 * GSTRIDE * 2);

    for (int it = 0; it <= T_STEPS; ++it) {
        // --- wait for group barrier: all 32 CTAs of this btile at phase >= it ---
        if (it > 0) {
            const unsigned phase = (unsigned)it;
            if (warp == 0) {
                for (;;) {
                    unsigned v = ld_acq(&grp_slots[lane]);   // 32 coalesced slots
                    if (__all_sync(0xffffffffu, v >= phase)) break;
                }
            }
            __syncthreads();
        }

        // --- issue multicast bulk loads: 8 rows/CTA, half-barrier per 16-row slab ---
        const __nv_bfloat16* Gc = g_G[it & 1];
        if (tid == 0) {
            asm volatile("fence.proxy.async;" ::: "memory");
            asm volatile("mbarrier.arrive.expect_tx.shared.b64 _, [%0], %1;"
                         :: "r"(mbar0), "r"(16 * ROW_BYTES) : "memory");
            asm volatile("mbarrier.arrive.expect_tx.shared.b64 _, [%0], %1;"
                         :: "r"(mbar1), "r"(16 * ROW_BYTES) : "memory");
            const uint32_t mb = (rank < 2) ? mbar0 : mbar1;
            #pragma unroll
            for (int rr = 0; rr < ROWS_PER_CTA; ++rr) {
                int r = rank * ROWS_PER_CTA + rr;
                const void* src = (const void*)(Gc + (size_t)(b0 + r) * SDIM);
                uint32_t dst = (uint32_t)__cvta_generic_to_shared(sG + r * GSTRIDE);
                asm volatile(
                    "cp.async.bulk.shared::cluster.global.mbarrier::complete_tx::bytes"
                    ".multicast::cluster [%0], [%1], %2, [%3], %4;"
                    :: "r"(dst), "l"(src), "r"(ROW_BYTES), "r"(mb),
                       "h"((unsigned short)((1u << CLUSTER) - 1u))
                    : "memory");
            }
        }

        // --- prefetch x for this step's outputs (hidden behind G delivery + mma) ---
        float xr[5];
        if (it >= 1) {
            #pragma unroll
            for (int d = 0; d < 5; ++d) {
                if (ej[d] >= SDIM) {
                    size_t oi = ((size_t)(it - 1) * BATCH + (b0 + ebl[d])) * ODIM + (ej[d] - SDIM);
                    xr[d] = __ldcs(x + oi);
                }
            }
        }

        float acc[2][5][4];
        #pragma unroll
        for (int mi = 0; mi < 2; ++mi)
            #pragma unroll
            for (int ni = 0; ni < 5; ++ni)
                #pragma unroll
                for (int q = 0; q < 4; ++q) acc[mi][ni][q] = 0.f;

        const unsigned parity = (unsigned)(it & 1);

        // --- half 0: rows 0-15 ---
        mbar_wait(mbar0, parity);
        #pragma unroll
        for (int ks = 0; ks < 8; ++ks) {
            unsigned a[4];
            ldsm_x4(a, aBase0 + ks * 32);
            #pragma unroll
            for (int ni = 0; ni < 5; ++ni)
                mma16816(acc[0][ni], a, Breg[ks][ni][0], Breg[ks][ni][1]);
        }
        // --- half 1: rows 16-31 ---
        mbar_wait(mbar1, parity);
        #pragma unroll
        for (int ks = 0; ks < 8; ++ks) {
            unsigned a[4];
            ldsm_x4(a, aBase1 + ks * 32);
            #pragma unroll
            for (int ni = 0; ni < 5; ++ni)
                mma16816(acc[1][ni], a, Breg[ks][ni][0], Breg[ks][ni][1]);
        }

        // --- write per-warp partials ---
        {
            float* p = sP + warp * (BT * JT);
            #pragma unroll
            for (int mi = 0; mi < 2; ++mi)
                #pragma unroll
                for (int ni = 0; ni < 5; ++ni) {
                    int r = mi * 16 + grp, cc = ni * 8 + tig * 2;
                    *(float2*)&p[r * JT + cc]       = make_float2(acc[mi][ni][0], acc[mi][ni][1]);
                    *(float2*)&p[(r + 8) * JT + cc] = make_float2(acc[mi][ni][2], acc[mi][ni][3]);
                }
        }
        __syncthreads();

        // consumer-only CTAs: all sG reads done -> arrive early (off critical path)
        if (!producer && tid == 0) st_rel(&grp_slots[jtile], (unsigned)(it + 1));

        // --- split-K reduce; h update + tanh + G store (critical path) ---
        __nv_bfloat16* Gn = g_G[(it + 1) & 1];
        float yv[5];
        #pragma unroll
        for (int d = 0; d < 5; ++d) {
            int e = d * NTHREADS + tid;
            float y = sP[e];
            #pragma unroll
            for (int w = 1; w < NWARPS; ++w) y += sP[w * (BT * JT) + e];
            yv[d] = y;
            if (ej[d] < SDIM) {
                float hv = 0.75f * hr[d] + 0.25f * (y + bv[d]);
                hr[d] = hv;
                Gn[(size_t)(b0 + ebl[d]) * SDIM + ej[d]] = __float2bfloat16(tanh_fast(hv));
            }
        }

        if (producer) {
            __syncthreads();
            if (tid == 0) st_rel(&grp_slots[jtile], (unsigned)(it + 1));
        }

        // --- outputs (off the critical path; x already in registers) ---
        if (it >= 1) {
            #pragma unroll
            for (int d = 0; d < 5; ++d) {
                if (ej[d] >= SDIM) {
                    size_t oi = ((size_t)(it - 1) * BATCH + (b0 + ebl[d])) * ODIM + (ej[d] - SDIM);
                    out[oi] = yv[d] + bv[d] - xr[d];
                }
            }
        }
    }

    // no CTA may exit while peers' multicast writes into its smem are possible
    asm volatile("barrier.cluster.arrive.aligned;" ::: "memory");
    asm volatile("barrier.cluster.wait.aligned;"   ::: "memory");
}

// ---------------- launch ----------------
extern "C" void kernel_launch(void* const* d_in, const int* in_sizes, int n_in,
                              void* d_out, int out_size) {
    const float *x = nullptr, *h = nullptr, *wr = nullptr, *br = nullptr,
                *wo = nullptr, *bo = nullptr;
    for (int i = 0; i < n_in; ++i) {
        switch (in_sizes[i]) {
            case 512 * 128 * 256: x  = (const float*)d_in[i]; break;  // 16777216
            case 128 * 1024:      h  = (const float*)d_in[i]; break;  // 131072
            case 1024 * 1024:     wr = (const float*)d_in[i]; break;  // 1048576
            case 1024:            br = (const float*)d_in[i]; break;
            case 256 * 1024:      wo = (const float*)d_in[i]; break;  // 262144
            case 256:             bo = (const float*)d_in[i]; break;
            default: break;
        }
    }
    cudaFuncSetAttribute(trnn_persistent,
                         cudaFuncAttributeMaxDynamicSharedMemorySize, SMEM_TOTAL);
    trnn_init<<<512, 256>>>(wr, wo, h);
    trnn_persistent<<<NCTAS, NTHREADS, SMEM_TOTAL>>>(x, h, br, bo, (float*)d_out);
}